// round 16
// baseline (speedup 1.0000x reference)
#include <cuda_runtime.h>
#include <cuda_bf16.h>
#include <cuda_fp16.h>
#include <cstdint>
#include <cstddef>

// Problem dims (fixed)
#define BB 16
#define SS 2048
#define LL 256
#define HH 768
#define CC 512
#define MROWS (BB*SS)   // 32768

typedef __nv_bfloat16  bf16;
typedef __nv_bfloat162 bf162;

// ---------------- one static scratch pool, byte-addressed -------------------
constexpr size_t SZ_IT     = (size_t)MROWS * CC * 2;
constexpr size_t SZ_FP     = (size_t)256 * CC * 4;
constexpr size_t SZ_FU     = (size_t)BB * CC * 4;
constexpr size_t SZ_X2     = (size_t)MROWS * HH * 2;
constexpr size_t SZ_LAB2   = (size_t)LL * HH * 2;
constexpr size_t SZ_WT2    = (size_t)CC * HH * 2;
constexpr size_t SZ_IA2    = (size_t)MROWS * CC * 2;
constexpr size_t SZ_ATT2   = (size_t)MROWS * LL * 2;
constexpr size_t SZ_LC2    = (size_t)LL * CC * 2;

constexpr size_t OFF_IT     = 0;
constexpr size_t OFF_FP     = OFF_IT + SZ_IT;
constexpr size_t OFF_FU     = OFF_FP + SZ_FP;
constexpr size_t OFF_XH     = OFF_FU + SZ_FU;
constexpr size_t OFF_LABH   = OFF_XH + SZ_X2;
constexpr size_t OFF_LABL   = OFF_LABH + SZ_LAB2;
constexpr size_t OFF_WIH    = OFF_LABL + SZ_LAB2;
constexpr size_t OFF_WLH    = OFF_WIH + SZ_WT2;
constexpr size_t OFF_WLL    = OFF_WLH + SZ_WT2;
constexpr size_t OFF_WIAH   = OFF_WLL + SZ_WT2;
constexpr size_t OFF_WLAH   = OFF_WIAH + SZ_WT2;
constexpr size_t OFF_WLAL   = OFF_WLAH + SZ_WT2;
constexpr size_t OFF_IAH    = OFF_WLAL + SZ_WT2;
constexpr size_t OFF_ATTH   = OFF_IAH + SZ_IA2;
constexpr size_t OFF_LTH    = OFF_ATTH + SZ_ATT2;
constexpr size_t OFF_LAH    = OFF_LTH + SZ_LC2;
constexpr size_t POOL_BYTES = OFF_LAH + SZ_LC2;

__device__ __align__(16) unsigned char g_pool[POOL_BYTES];

// ---------------- helpers ---------------------------------------------------
__device__ __forceinline__ uint32_t smem_u32(const void* p) {
    uint32_t a;
    asm("{ .reg .u64 t; cvta.to.shared.u64 t, %1; cvt.u32.u64 %0, t; }" : "=r"(a) : "l"(p));
    return a;
}
__device__ __forceinline__ void cp16(uint32_t dst, const void* src) {
    asm volatile("cp.async.cg.shared.global [%0], [%1], 16;" :: "r"(dst), "l"(src) : "memory");
}
__device__ __forceinline__ void cp32(uint32_t dst, const void* src) {
    cp16(dst, src);
    cp16(dst + 16, (const char*)src + 16);
}
#define CP_COMMIT() asm volatile("cp.async.commit_group;" ::: "memory")
#define CP_WAIT0()  asm volatile("cp.async.wait_group 0;"  ::: "memory")

#define LDSM4(R0,R1,R2,R3,ADDR) \
    asm volatile("ldmatrix.sync.aligned.m8n8.x4.shared.b16 {%0,%1,%2,%3}, [%4];" \
                 : "=r"(R0),"=r"(R1),"=r"(R2),"=r"(R3) : "r"(ADDR))

#define MMA_BF16(C,A,B0,B1) \
    asm volatile("mma.sync.aligned.m16n8k16.row.col.f32.bf16.bf16.f32 " \
                 "{%0,%1,%2,%3},{%4,%5,%6,%7},{%8,%9},{%0,%1,%2,%3};" \
                 : "+f"((C)[0]),"+f"((C)[1]),"+f"((C)[2]),"+f"((C)[3]) \
                 : "r"((A)[0]),"r"((A)[1]),"r"((A)[2]),"r"((A)[3]), \
                   "r"(B0),"r"(B1))

#define MMA_F16F32(C,A,B0,B1) \
    asm volatile("mma.sync.aligned.m16n8k16.row.col.f32.f16.f16.f32 " \
                 "{%0,%1,%2,%3},{%4,%5,%6,%7},{%8,%9},{%0,%1,%2,%3};" \
                 : "+f"((C)[0]),"+f"((C)[1]),"+f"((C)[2]),"+f"((C)[3]) \
                 : "r"((A)[0]),"r"((A)[1]),"r"((A)[2]),"r"((A)[3]), \
                   "r"(B0),"r"(B1))

#define MMA_F16ACC(C0,C1,A,B0,B1) \
    asm volatile("mma.sync.aligned.m16n8k16.row.col.f16.f16.f16.f16 " \
                 "{%0,%1},{%2,%3,%4,%5},{%6,%7},{%0,%1};" \
                 : "+r"(C0),"+r"(C1) \
                 : "r"((A)[0]),"r"((A)[1]),"r"((A)[2]),"r"((A)[3]), \
                   "r"(B0),"r"(B1))

__device__ __forceinline__ void bsplit(float v, bf16& h, bf16& l) {
    h = __float2bfloat16(v);
    l = __float2bfloat16(v - __bfloat162float(h));
}
__device__ __forceinline__ float sigmoidf_(float v) {
    return 1.0f / (1.0f + __expf(-v));
}
// online softmax stat merge: (m,s) <- merge((m,s),(om,os))
__device__ __forceinline__ void sm_merge(float& m, float& s, float om, float os) {
    float M = fmaxf(m, om);
    s = s * __expf(m - M) + os * __expf(om - M);
    m = M;
}

// ---------------- input conversion kernels -----------------------------------
__global__ __launch_bounds__(256)
void ksplit(const float4* __restrict__ src, size_t oHi, size_t oLo, int n4)
{
    int i = blockIdx.x * 256 + threadIdx.x;
    if (i >= n4) return;
    bf162* hi = (bf162*)(g_pool + oHi);
    bf162* lo = (bf162*)(g_pool + oLo);
    float4 v = src[i];
    bf16 h0, l0, h1, l1, h2, l2, h3, l3;
    bsplit(v.x, h0, l0); bsplit(v.y, h1, l1);
    bsplit(v.z, h2, l2); bsplit(v.w, h3, l3);
    hi[i * 2 + 0] = __halves2bfloat162(h0, h1);
    hi[i * 2 + 1] = __halves2bfloat162(h2, h3);
    lo[i * 2 + 0] = __halves2bfloat162(l0, l1);
    lo[i * 2 + 1] = __halves2bfloat162(l2, l3);
}

__global__ __launch_bounds__(256)
void kconv_f16(const float4* __restrict__ src, size_t oH, int n4)
{
    int i = blockIdx.x * 256 + threadIdx.x;
    if (i >= n4) return;
    half2* h = (half2*)(g_pool + oH);
    float4 v = src[i];
    h[i * 2 + 0] = __floats2half2_rn(v.x, v.y);
    h[i * 2 + 1] = __floats2half2_rn(v.z, v.w);
}

// ---------------- shared tile geometry ---------------------------------------
#define SROW  80
#define TILEB (128 * SROW)  // 10240

enum { EPI_SIGC = 1, EPI_SIGR = 3 };

// ---------------- bf16 3-product GEMM (G1/G2), fp16 out ----------------------
#define STAGEB (4 * TILEB)
#define GSMEM (2 * STAGEB)  // 81920

template<int EPI>
__global__ __launch_bounds__(256, 2)
void mma_gemm_b3(size_t oAh, size_t oAl, size_t oBh, size_t oBl,
                 size_t oCh, int M, int N, int K,
                 const float* __restrict__ bias)
{
    const bf16* Ah = (const bf16*)(g_pool + oAh);
    const bf16* Al = (const bf16*)(g_pool + oAl);
    const bf16* Bh = (const bf16*)(g_pool + oBh);
    const bf16* Bl = (const bf16*)(g_pool + oBl);
    __half* Ch = (__half*)(g_pool + oCh);

    extern __shared__ char smem[];
    const uint32_t sb = smem_u32(smem);
    const int tid  = threadIdx.x;
    const int lane = tid & 31;
    const int wid  = tid >> 5;
    const int wm   = wid & 3;
    const int wn   = wid >> 2;
    const int m0 = blockIdx.y * 128;
    const int n0 = blockIdx.x * 128;

    const int lr = tid >> 1;
    const int lh = tid & 1;
    const bf16* gAh = Ah + (size_t)(m0 + lr) * K + lh * 16;
    const bf16* gAl = Al + (size_t)(m0 + lr) * K + lh * 16;
    const bf16* gBh = Bh + (size_t)(n0 + lr) * K + lh * 16;
    const bf16* gBl = Bl + (size_t)(n0 + lr) * K + lh * 16;
    const uint32_t sdst = (uint32_t)(lr * SROW + lh * 32);

    const int NCH = K / 32;
    float c[2][8][4] = {};

    {
        uint32_t d = sb + sdst;
        cp32(d,             gAh);
        cp32(d + TILEB,     gAl);
        cp32(d + 2 * TILEB, gBh);
        cp32(d + 3 * TILEB, gBl);
        CP_COMMIT();
        CP_WAIT0();
        __syncthreads();
    }

    for (int ch = 0; ch < NCH; ch++) {
        if (ch + 1 < NCH) {
            const int k0 = (ch + 1) * 32;
            uint32_t d = sb + ((ch + 1) & 1) * STAGEB + sdst;
            cp32(d,             gAh + k0);
            cp32(d + TILEB,     gAl + k0);
            cp32(d + 2 * TILEB, gBh + k0);
            cp32(d + 3 * TILEB, gBl + k0);
            CP_COMMIT();
        }

        const uint32_t base = sb + (ch & 1) * STAGEB;
        #pragma unroll
        for (int ks = 0; ks < 2; ks++) {
            uint32_t ah[2][4], al[2][4];
            #pragma unroll
            for (int mf = 0; mf < 2; mf++) {
                uint32_t addr = base
                    + (uint32_t)((wm * 32 + mf * 16 + (lane & 15)) * SROW)
                    + (uint32_t)(ks * 32 + (lane >> 4) * 16);
                LDSM4(ah[mf][0], ah[mf][1], ah[mf][2], ah[mf][3], addr);
                LDSM4(al[mf][0], al[mf][1], al[mf][2], al[mf][3], addr + TILEB);
            }
            const int g = lane >> 3;
            #pragma unroll
            for (int p = 0; p < 4; p++) {
                uint32_t addr = base + 2 * TILEB
                    + (uint32_t)((wn * 64 + p * 16 + ((g & 2) ? 8 : 0) + (lane & 7)) * SROW)
                    + (uint32_t)(ks * 32 + (g & 1) * 16);
                uint32_t h0, h1, h2, h3, l0, l1, l2, l3;
                LDSM4(h0, h1, h2, h3, addr);
                LDSM4(l0, l1, l2, l3, addr + TILEB);
                #pragma unroll
                for (int mf = 0; mf < 2; mf++) {
                    MMA_BF16(c[mf][2*p],   ah[mf], h0, h1);
                    MMA_BF16(c[mf][2*p],   ah[mf], l0, l1);
                    MMA_BF16(c[mf][2*p],   al[mf], h0, h1);
                    MMA_BF16(c[mf][2*p+1], ah[mf], h2, h3);
                    MMA_BF16(c[mf][2*p+1], ah[mf], l2, l3);
                    MMA_BF16(c[mf][2*p+1], al[mf], h2, h3);
                }
            }
        }
        if (ch + 1 < NCH) CP_WAIT0();
        __syncthreads();
    }

    const int quad = lane >> 2;
    const int tq   = lane & 3;
    #pragma unroll
    for (int mf = 0; mf < 2; mf++) {
        const int r0 = m0 + wm * 32 + mf * 16 + quad;
        const int r1 = r0 + 8;
        float rb0 = 0.f, rb1 = 0.f;
        if (EPI == EPI_SIGR) { rb0 = bias[r0]; rb1 = bias[r1]; }
        #pragma unroll
        for (int nf = 0; nf < 8; nf++) {
            const int col = n0 + wn * 64 + nf * 8 + tq * 2;
            float v0 = c[mf][nf][0], v1 = c[mf][nf][1];
            float v2 = c[mf][nf][2], v3 = c[mf][nf][3];
            if (EPI == EPI_SIGC) {
                float2 bb = *(const float2*)(bias + col);
                v0 = sigmoidf_(v0 + bb.x); v1 = sigmoidf_(v1 + bb.y);
                v2 = sigmoidf_(v2 + bb.x); v3 = sigmoidf_(v3 + bb.y);
            } else {
                v0 = sigmoidf_(v0 + rb0); v1 = sigmoidf_(v1 + rb0);
                v2 = sigmoidf_(v2 + rb1); v3 = sigmoidf_(v3 + rb1);
            }
            *(half2*)(Ch + (size_t)r0 * N + col) = __floats2half2_rn(v0, v1);
            *(half2*)(Ch + (size_t)r1 * N + col) = __floats2half2_rn(v2, v3);
        }
    }
}

// ---------------- fused G5 + softmax: attn = softmax(ia @ la^T) --------------
// One CTA per 128 rows; two 128-col passes; in-CTA softmax; fp16 attn out.
#define G5TILES (2 * TILEB)                 // A + B per stage
#define SM_LG   (2 * G5TILES)               // 40960 (2 stages of tiles)
#define SZ_LG   (128 * 128 * 2)             // 32768, fp16 pass-1 logits
#define SM_REDA (SM_LG + SZ_LG)             // float2 redA[128]   (smem half)
#define SM_RED2 (SM_REDA + 128 * 8)         // float2 red2[128][2] (reg half / wn)
#define SM_REDF (SM_RED2 + 256 * 8)         // float2 redf[128]   (M, 1/S)
#define G5SMEM  (SM_REDF + 128 * 8)         // 40960+32768+1024+2048+1024 = 77824

__global__ __launch_bounds__(256, 2)
void mma_g5sm()
{
    const __half* Ain = (const __half*)(g_pool + OFF_IAH);
    const __half* Bin = (const __half*)(g_pool + OFF_LAH);
    __half* atth = (__half*)(g_pool + OFF_ATTH);

    extern __shared__ char smem[];
    const uint32_t sb = smem_u32(smem);
    __half* lg = (__half*)(smem + SM_LG);
    float2* redA = (float2*)(smem + SM_REDA);
    float2* red2 = (float2*)(smem + SM_RED2);
    float2* redf = (float2*)(smem + SM_REDF);

    const int tid  = threadIdx.x;
    const int lane = tid & 31;
    const int wid  = tid >> 5;
    const int wm   = wid & 3;
    const int wn   = wid >> 2;
    const int m0 = blockIdx.x * 128;
    const int quad = lane >> 2;
    const int tq   = lane & 3;
    const int K = CC;   // 512

    const int lr = tid >> 1;
    const int lh = tid & 1;
    const __half* gA = Ain + (size_t)(m0 + lr) * K + lh * 16;
    const uint32_t sdst = (uint32_t)(lr * SROW + lh * 32);

    float c[2][8][4];   // current pass accumulators

    for (int pass = 0; pass < 2; pass++) {
        const int n0 = pass * 128;
        const __half* gB = Bin + (size_t)(n0 + lr) * K + lh * 16;
        #pragma unroll
        for (int mf = 0; mf < 2; mf++)
            #pragma unroll
            for (int nf = 0; nf < 8; nf++)
                #pragma unroll
                for (int q = 0; q < 4; q++)
                    c[mf][nf][q] = 0.0f;

        {
            uint32_t d = sb + sdst;
            cp32(d,         gA);
            cp32(d + TILEB, gB);
            CP_COMMIT();
            CP_WAIT0();
            __syncthreads();
        }

        const int NCH = K / 32;   // 16
        for (int ch = 0; ch < NCH; ch++) {
            if (ch + 1 < NCH) {
                const int k0 = (ch + 1) * 32;
                uint32_t d = sb + ((ch + 1) & 1) * G5TILES + sdst;
                cp32(d,         gA + k0);
                cp32(d + TILEB, gB + k0);
                CP_COMMIT();
            }
            const uint32_t base = sb + (ch & 1) * G5TILES;
            #pragma unroll
            for (int ks = 0; ks < 2; ks++) {
                uint32_t ah[2][4];
                #pragma unroll
                for (int mf = 0; mf < 2; mf++) {
                    uint32_t addr = base
                        + (uint32_t)((wm * 32 + mf * 16 + (lane & 15)) * SROW)
                        + (uint32_t)(ks * 32 + (lane >> 4) * 16);
                    LDSM4(ah[mf][0], ah[mf][1], ah[mf][2], ah[mf][3], addr);
                }
                const int g = lane >> 3;
                #pragma unroll
                for (int p = 0; p < 4; p++) {
                    uint32_t addr = base + TILEB
                        + (uint32_t)((wn * 64 + p * 16 + ((g & 2) ? 8 : 0) + (lane & 7)) * SROW)
                        + (uint32_t)(ks * 32 + (g & 1) * 16);
                    uint32_t h0, h1, h2, h3;
                    LDSM4(h0, h1, h2, h3, addr);
                    #pragma unroll
                    for (int mf = 0; mf < 2; mf++) {
                        MMA_F16F32(c[mf][2*p],   ah[mf], h0, h1);
                        MMA_F16F32(c[mf][2*p+1], ah[mf], h2, h3);
                    }
                }
            }
            if (ch + 1 < NCH) CP_WAIT0();
            __syncthreads();
        }

        if (pass == 0) {
            // stash pass-1 logits (local cols 0..127) to smem fp16
            #pragma unroll
            for (int mf = 0; mf < 2; mf++) {
                const int r0l = wm * 32 + mf * 16 + quad;
                const int r1l = r0l + 8;
                #pragma unroll
                for (int nf = 0; nf < 8; nf++) {
                    const int col = wn * 64 + nf * 8 + tq * 2;
                    *(half2*)(lg + (size_t)r0l * 128 + col) =
                        __floats2half2_rn(c[mf][nf][0], c[mf][nf][1]);
                    *(half2*)(lg + (size_t)r1l * 128 + col) =
                        __floats2half2_rn(c[mf][nf][2], c[mf][nf][3]);
                }
            }
            // no sync needed here: pass-2 prologue sync orders these writes
        }
    }

    // ---- softmax over 256 cols per row (smem half + register half) ----------
    __syncthreads();   // ensure pass-1 logits visible to all

    // Phase A: smem-half stats; 2 threads per row, 64 cols each
    {
        const int row = tid >> 1;
        const int hc  = tid & 1;
        const half2* rp = (const half2*)(lg + (size_t)row * 128) + hc * 32;
        float m = -1e30f;
        #pragma unroll 8
        for (int j = 0; j < 32; j++) {
            float2 v = __half22float2(rp[j]);
            m = fmaxf(m, fmaxf(v.x, v.y));
        }
        float s = 0.0f;
        #pragma unroll 8
        for (int j = 0; j < 32; j++) {
            float2 v = __half22float2(rp[j]);
            s += __expf(v.x - m) + __expf(v.y - m);
        }
        float om = __shfl_xor_sync(0xffffffff, m, 1);
        float os = __shfl_xor_sync(0xffffffff, s, 1);
        sm_merge(m, s, om, os);
        if (hc == 0) redA[row] = make_float2(m, s);
    }

    // Phase B: register-half stats (pass-2 accumulators, local cols 0..127 -> global 128..255)
    {
        float rm[2][2], rs[2][2];
        #pragma unroll
        for (int mf = 0; mf < 2; mf++) {
            float m0v = -1e30f, m1v = -1e30f;
            #pragma unroll
            for (int nf = 0; nf < 8; nf++) {
                m0v = fmaxf(m0v, fmaxf(c[mf][nf][0], c[mf][nf][1]));
                m1v = fmaxf(m1v, fmaxf(c[mf][nf][2], c[mf][nf][3]));
            }
            float s0v = 0.f, s1v = 0.f;
            #pragma unroll
            for (int nf = 0; nf < 8; nf++) {
                s0v += __expf(c[mf][nf][0] - m0v) + __expf(c[mf][nf][1] - m0v);
                s1v += __expf(c[mf][nf][2] - m1v) + __expf(c[mf][nf][3] - m1v);
            }
            rm[mf][0] = m0v; rs[mf][0] = s0v;
            rm[mf][1] = m1v; rs[mf][1] = s1v;
        }
        // merge across tq lanes (xor 1 then 2)
        #pragma unroll
        for (int st = 1; st <= 2; st <<= 1) {
            #pragma unroll
            for (int mf = 0; mf < 2; mf++)
                #pragma unroll
                for (int rr = 0; rr < 2; rr++) {
                    float om = __shfl_xor_sync(0xffffffff, rm[mf][rr], st);
                    float os = __shfl_xor_sync(0xffffffff, rs[mf][rr], st);
                    sm_merge(rm[mf][rr], rs[mf][rr], om, os);
                }
        }
        if (tq == 0) {
            #pragma unroll
            for (int mf = 0; mf < 2; mf++) {
                const int r0l = wm * 32 + mf * 16 + quad;
                red2[r0l * 2 + wn]       = make_float2(rm[mf][0], rs[mf][0]);
                red2[(r0l + 8) * 2 + wn] = make_float2(rm[mf][1], rs[mf][1]);
            }
        }
    }
    __syncthreads();

    // Phase C: final (M, 1/S) per row
    if (tid < 128) {
        float2 a = redA[tid];
        float2 b = red2[tid * 2 + 0];
        float2 d = red2[tid * 2 + 1];
        float m = a.x, s = a.y;
        sm_merge(m, s, b.x, b.y);
        sm_merge(m, s, d.x, d.y);
        redf[tid] = make_float2(m, 1.0f / s);
    }
    __syncthreads();

    // Phase D: write attn fp16
    // register half -> global cols 128..255
    #pragma unroll
    for (int mf = 0; mf < 2; mf++) {
        const int r0l = wm * 32 + mf * 16 + quad;
        const int r1l = r0l + 8;
        float2 f0 = redf[r0l];
        float2 f1 = redf[r1l];
        #pragma unroll
        for (int nf = 0; nf < 8; nf++) {
            const int col = wn * 64 + nf * 8 + tq * 2;
            float p0 = __expf(c[mf][nf][0] - f0.x) * f0.y;
            float p1 = __expf(c[mf][nf][1] - f0.x) * f0.y;
            float p2 = __expf(c[mf][nf][2] - f1.x) * f1.y;
            float p3 = __expf(c[mf][nf][3] - f1.x) * f1.y;
            *(half2*)(atth + (size_t)(m0 + r0l) * LL + 128 + col) = __floats2half2_rn(p0, p1);
            *(half2*)(atth + (size_t)(m0 + r1l) * LL + 128 + col) = __floats2half2_rn(p2, p3);
        }
    }
    // smem half -> global cols 0..127
    {
        const int row = tid >> 1;
        const int hc  = tid & 1;
        float2 f = redf[row];
        const half2* rp = (const half2*)(lg + (size_t)row * 128) + hc * 32;
        half2* op = (half2*)(atth + (size_t)(m0 + row) * LL + hc * 64);
        #pragma unroll 8
        for (int j = 0; j < 32; j++) {
            float2 v = __half22float2(rp[j]);
            op[j] = __floats2half2_rn(__expf(v.x - f.x) * f.y,
                                      __expf(v.y - f.x) * f.y);
        }
    }
}

// ---------------- dual GEMM: 256 thr, occ 2; both outputs per warp -----------
#define DSTAGEB (3 * TILEB)       // 30720
#define DGSMEM  (2 * DSTAGEB)     // 61440

__global__ __launch_bounds__(256, 2)
void mma_gemm_dual2(const float* __restrict__ bias_i,
                    const float* __restrict__ bias_ia,
                    const float* __restrict__ ctx)
{
    extern __shared__ char smem[];
    const uint32_t sb = smem_u32(smem);
    const int tid  = threadIdx.x;
    const int lane = tid & 31;
    const int wid  = tid >> 5;
    const int wm   = wid & 3;
    const int wn   = wid >> 2;
    const int m0 = blockIdx.y * 128;
    const int n0 = blockIdx.x * 128;
    const int K = HH;

    const __half* srcp[6];
    uint32_t dstp[6];
    {
        const __half* baseA  = (const __half*)(g_pool + OFF_XH);
        const __half* baseB0 = (const __half*)(g_pool + OFF_WIH);
        const __half* baseB1 = (const __half*)(g_pool + OFF_WIAH);
        #pragma unroll
        for (int t = 0; t < 6; t++) {
            int c2 = tid + t * 256;
            int tile = c2 >> 9;
            int pos  = c2 & 511;
            int row  = pos >> 2;
            int q    = pos & 3;
            const __half* bp;
            int rbase;
            switch (tile) {
                case 0: bp = baseA;  rbase = m0; break;
                case 1: bp = baseB0; rbase = n0; break;
                default: bp = baseB1; rbase = n0; break;
            }
            srcp[t] = bp + (size_t)(rbase + row) * K + q * 8;
            dstp[t] = (uint32_t)(tile * TILEB + row * SROW + q * 16);
        }
    }

    const int NCH = K / 32;
    uint32_t cit[2][8][2] = {};
    uint32_t cia[2][8][2] = {};

    {
        #pragma unroll
        for (int t = 0; t < 6; t++)
            cp16(sb + dstp[t], srcp[t]);
        CP_COMMIT();
        CP_WAIT0();
        __syncthreads();
    }

    for (int ch = 0; ch < NCH; ch++) {
        if (ch + 1 < NCH) {
            const int k0 = (ch + 1) * 32;
            const uint32_t stg = sb + ((ch + 1) & 1) * DSTAGEB;
            #pragma unroll
            for (int t = 0; t < 6; t++)
                cp16(stg + dstp[t], srcp[t] + k0);
            CP_COMMIT();
        }

        const uint32_t base = sb + (ch & 1) * DSTAGEB;
        #pragma unroll
        for (int ks = 0; ks < 2; ks++) {
            uint32_t ah[2][4];
            #pragma unroll
            for (int mf = 0; mf < 2; mf++) {
                uint32_t addr = base
                    + (uint32_t)((wm * 32 + mf * 16 + (lane & 15)) * SROW)
                    + (uint32_t)(ks * 32 + (lane >> 4) * 16);
                LDSM4(ah[mf][0], ah[mf][1], ah[mf][2], ah[mf][3], addr);
            }
            const int g = lane >> 3;
            #pragma unroll
            for (int p = 0; p < 4; p++) {
                uint32_t addr = base + TILEB
                    + (uint32_t)((wn * 64 + p * 16 + ((g & 2) ? 8 : 0) + (lane & 7)) * SROW)
                    + (uint32_t)(ks * 32 + (g & 1) * 16);
                uint32_t h0, h1, h2, h3;
                LDSM4(h0, h1, h2, h3, addr);
                #pragma unroll
                for (int mf = 0; mf < 2; mf++) {
                    MMA_F16ACC(cit[mf][2*p][0],   cit[mf][2*p][1],   ah[mf], h0, h1);
                    MMA_F16ACC(cit[mf][2*p+1][0], cit[mf][2*p+1][1], ah[mf], h2, h3);
                }
                LDSM4(h0, h1, h2, h3, addr + TILEB);
                #pragma unroll
                for (int mf = 0; mf < 2; mf++) {
                    MMA_F16ACC(cia[mf][2*p][0],   cia[mf][2*p][1],   ah[mf], h0, h1);
                    MMA_F16ACC(cia[mf][2*p+1][0], cia[mf][2*p+1][1], ah[mf], h2, h3);
                }
            }
        }
        if (ch + 1 < NCH) CP_WAIT0();
        __syncthreads();
    }

    const int quad = lane >> 2;
    const int tq   = lane & 3;
    __half* Cit = (__half*)(g_pool + OFF_IT);
    __half* Cia = (__half*)(g_pool + OFF_IAH);
    #pragma unroll
    for (int mf = 0; mf < 2; mf++) {
        const int r0 = m0 + wm * 32 + mf * 16 + quad;
        const int r1 = r0 + 8;
        #pragma unroll
        for (int nf = 0; nf < 8; nf++) {
            const int col = n0 + wn * 64 + nf * 8 + tq * 2;
            float2 bbi = *(const float2*)(bias_i + col);
            float2 bba = *(const float2*)(bias_ia + col);
            float2 ss  = *(const float2*)(ctx + col);
            float2 a01 = __half22float2(*(half2*)&cit[mf][nf][0]);
            float2 a23 = __half22float2(*(half2*)&cit[mf][nf][1]);
            *(half2*)(Cit + (size_t)r0 * CC + col) =
                __floats2half2_rn(sigmoidf_(a01.x + bbi.x), sigmoidf_(a01.y + bbi.y));
            *(half2*)(Cit + (size_t)r1 * CC + col) =
                __floats2half2_rn(sigmoidf_(a23.x + bbi.x), sigmoidf_(a23.y + bbi.y));
            a01 = __half22float2(*(half2*)&cia[mf][nf][0]);
            a23 = __half22float2(*(half2*)&cia[mf][nf][1]);
            *(half2*)(Cia + (size_t)r0 * CC + col) =
                __floats2half2_rn(sigmoidf_(a01.x + bba.x) * ss.x,
                                  sigmoidf_(a01.y + bba.y) * ss.y);
            *(half2*)(Cia + (size_t)r1 * CC + col) =
                __floats2half2_rn(sigmoidf_(a23.x + bba.x) * ss.x,
                                  sigmoidf_(a23.y + bba.y) * ss.y);
        }
    }
}

// ---------------- G7 + fusion (fp16 in, fp16 accum) --------------------------
#define FSTAGE (2 * TILEB)
#define F7SMEM (2 * FSTAGE + 4 * 128 * 4)  // 43008

__global__ __launch_bounds__(256, 2)
void mma_gemm_fuse()
{
    const __half* Ah = (const __half*)(g_pool + OFF_ATTH);
    const __half* Bh = (const __half*)(g_pool + OFF_LTH);
    const __half* itp = (const __half*)(g_pool + OFF_IT);
    float* fpart = (float*)(g_pool + OFF_FP);

    extern __shared__ char smem[];
    const uint32_t sb = smem_u32(smem);
    float* facc = (float*)(smem + 2 * FSTAGE);
    const int tid  = threadIdx.x;
    const int lane = tid & 31;
    const int wid  = tid >> 5;
    const int wm   = wid & 3;
    const int wn   = wid >> 2;
    const int m0 = blockIdx.y * 128;
    const int n0 = blockIdx.x * 128;
    const int K = LL;

    const int lr = tid >> 1;
    const int lh = tid & 1;
    const __half* gAh = Ah + (size_t)(m0 + lr) * K + lh * 16;
    const __half* gBh = Bh + (size_t)(n0 + lr) * K + lh * 16;
    const uint32_t sdst = (uint32_t)(lr * SROW + lh * 32);

    const int NCH = K / 32;
    uint32_t c[2][8][2] = {};

    {
        uint32_t d = sb + sdst;
        cp32(d,         gAh);
        cp32(d + TILEB, gBh);
        CP_COMMIT();
        CP_WAIT0();
        __syncthreads();
    }

    for (int ch = 0; ch < NCH; ch++) {
        if (ch + 1 < NCH) {
            const int k0 = (ch + 1) * 32;
            uint32_t d = sb + ((ch + 1) & 1) * FSTAGE + sdst;
            cp32(d,         gAh + k0);
            cp32(d + TILEB, gBh + k0);
            CP_COMMIT();
        }

        const uint32_t base = sb + (ch & 1) * FSTAGE;
        #pragma unroll
        for (int ks = 0; ks < 2; ks++) {
            uint32_t ah[2][4];
            #pragma unroll
            for (int mf = 0; mf < 2; mf++) {
                uint32_t addr = base
                    + (uint32_t)((wm * 32 + mf * 16 + (lane & 15)) * SROW)
                    + (uint32_t)(ks * 32 + (lane >> 4) * 16);
                LDSM4(ah[mf][0], ah[mf][1], ah[mf][2], ah[mf][3], addr);
            }
            const int g = lane >> 3;
            #pragma unroll
            for (int p = 0; p < 4; p++) {
                uint32_t addr = base + TILEB
                    + (uint32_t)((wn * 64 + p * 16 + ((g & 2) ? 8 : 0) + (lane & 7)) * SROW)
                    + (uint32_t)(ks * 32 + (g & 1) * 16);
                uint32_t h0, h1, h2, h3;
                LDSM4(h0, h1, h2, h3, addr);
                #pragma unroll
                for (int mf = 0; mf < 2; mf++) {
                    MMA_F16ACC(c[mf][2*p][0],   c[mf][2*p][1],   ah[mf], h0, h1);
                    MMA_F16ACC(c[mf][2*p+1][0], c[mf][2*p+1][1], ah[mf], h2, h3);
                }
            }
        }
        if (ch + 1 < NCH) CP_WAIT0();
        __syncthreads();
    }

    const int quad = lane >> 2;
    const int tq   = lane & 3;
    float pc[16];
    #pragma unroll
    for (int i = 0; i < 16; i++) pc[i] = 0.0f;
    #pragma unroll
    for (int mf = 0; mf < 2; mf++) {
        const int r0g = m0 + wm * 32 + mf * 16 + quad;
        const int r1g = r0g + 8;
        #pragma unroll
        for (int nf = 0; nf < 8; nf++) {
            const int colg = n0 + wn * 64 + nf * 8 + tq * 2;
            float2 w01 = __half22float2(*(half2*)&c[mf][nf][0]);
            float2 w23 = __half22float2(*(half2*)&c[mf][nf][1]);
            float2 i0 = __half22float2(*(const half2*)(itp + (size_t)r0g * CC + colg));
            float2 i1 = __half22float2(*(const half2*)(itp + (size_t)r1g * CC + colg));
            pc[2*nf]   += w01.x * i0.x + w23.x * i1.x;
            pc[2*nf+1] += w01.y * i0.y + w23.y * i1.y;
        }
    }
    #pragma unroll
    for (int off = 4; off <= 16; off <<= 1)
        #pragma unroll
        for (int i = 0; i < 16; i++)
            pc[i] += __shfl_xor_sync(0xffffffff, pc[i], off);
    if (quad == 0) {
        #pragma unroll
        for (int nf = 0; nf < 8; nf++) {
            const int col = wn * 64 + nf * 8 + tq * 2;
            facc[wm * 128 + col]     = pc[2*nf];
            facc[wm * 128 + col + 1] = pc[2*nf+1];
        }
    }
    __syncthreads();
    if (tid < 128) {
        float s = facc[tid] + facc[128 + tid] + facc[256 + tid] + facc[384 + tid];
        fpart[(size_t)blockIdx.y * CC + n0 + tid] = s;
    }
}

// ---------------- fusion reduce ----------------------------------------------
__global__ __launch_bounds__(512)
void fusion_reduce()
{
    const float* fp = (const float*)(g_pool + OFF_FP);
    float* fu = (float*)(g_pool + OFF_FU);
    const int b = blockIdx.x, cidx = threadIdx.x;
    float acc = 0.0f;
    #pragma unroll
    for (int k = 0; k < 16; k++)
        acc += fp[((size_t)b * 16 + k) * CC + cidx];
    fu[(size_t)b * CC + cidx] = acc;
}

// ---------------- final: out[b,h] = sum_c fusion[b,c] * Wp[h,c] -------------
__global__ __launch_bounds__(256)
void final_gemm(const float* __restrict__ Wp, float* __restrict__ out)
{
    __shared__ float fs[CC];
    const float* fu = (const float*)(g_pool + OFF_FU);
    const int b = blockIdx.x;
    const int h = blockIdx.y * 256 + threadIdx.x;

    for (int i = threadIdx.x; i < CC; i += 256)
        fs[i] = fu[(size_t)b * CC + i];
    __syncthreads();

    float acc = 0.0f;
    const float4* wp4 = (const float4*)(Wp + (size_t)h * CC);
    const float4* fs4 = (const float4*)fs;
    #pragma unroll 4
    for (int c4 = 0; c4 < CC / 4; c4++) {
        float4 w = wp4[c4], f = fs4[c4];
        acc += w.x * f.x + w.y * f.y + w.z * f.z + w.w * f.w;
    }
    out[(size_t)b * HH + h] = acc;
}

// ---------------- launch ----------------------------------------------------
extern "C" void kernel_launch(void* const* d_in, const int* in_sizes, int n_in,
                              void* d_out, int out_size)
{
    const float* x   = (const float*)d_in[0];
    const float* lab = (const float*)d_in[1];
    const float* Wi  = (const float*)d_in[2];
    const float* bi  = (const float*)d_in[3];
    const float* Wl  = (const float*)d_in[4];
    const float* bl  = (const float*)d_in[5];
    const float* Wia = (const float*)d_in[6];
    const float* bia = (const float*)d_in[7];
    const float* Wla = (const float*)d_in[8];
    const float* bla = (const float*)d_in[9];
    const float* ctx = (const float*)d_in[10];
    const float* Wp  = (const float*)d_in[11];
    float* out = (float*)d_out;

    cudaFuncSetAttribute(mma_gemm_b3<EPI_SIGR>, cudaFuncAttributeMaxDynamicSharedMemorySize, GSMEM);
    cudaFuncSetAttribute(mma_gemm_b3<EPI_SIGC>, cudaFuncAttributeMaxDynamicSharedMemorySize, GSMEM);
    cudaFuncSetAttribute(mma_g5sm,       cudaFuncAttributeMaxDynamicSharedMemorySize, G5SMEM);
    cudaFuncSetAttribute(mma_gemm_dual2, cudaFuncAttributeMaxDynamicSharedMemorySize, DGSMEM);
    cudaFuncSetAttribute(mma_gemm_fuse,  cudaFuncAttributeMaxDynamicSharedMemorySize, F7SMEM);

    // ---- input conversions ----
    kconv_f16<<<(MROWS * HH / 4 + 255) / 256, 256>>>((const float4*)x,   OFF_XH,   MROWS * HH / 4);
    kconv_f16<<<(CC * HH / 4 + 255) / 256, 256>>>((const float4*)Wi,  OFF_WIH,  CC * HH / 4);
    kconv_f16<<<(CC * HH / 4 + 255) / 256, 256>>>((const float4*)Wia, OFF_WIAH, CC * HH / 4);
    ksplit<<<(LL * HH / 4 + 255) / 256, 256>>>((const float4*)lab, OFF_LABH, OFF_LABL, LL * HH / 4);
    ksplit<<<(CC * HH / 4 + 255) / 256, 256>>>((const float4*)Wl,  OFF_WLH,  OFF_WLL,  CC * HH / 4);
    ksplit<<<(CC * HH / 4 + 255) / 256, 256>>>((const float4*)Wla, OFF_WLAH, OFF_WLAL, CC * HH / 4);

    // ---- fused G3+G4: it, ia' (fp16, occ-2 dual) ----
    mma_gemm_dual2<<<dim3(CC / 128, MROWS / 128), 256, DGSMEM>>>(bi, bia, ctx);

    // ---- G1: ltT (bf16 3-product, fp16 out) ----
    mma_gemm_b3<EPI_SIGR><<<dim3(LL / 128, CC / 128), 256, GSMEM>>>(
        OFF_WLH, OFF_WLL, OFF_LABH, OFF_LABL, OFF_LTH, CC, LL, HH, bl);

    // ---- G2: la (bf16 3-product, fp16 out) ----
    mma_gemm_b3<EPI_SIGC><<<dim3(CC / 128, LL / 128), 256, GSMEM>>>(
        OFF_LABH, OFF_LABL, OFF_WLAH, OFF_WLAL, OFF_LAH, LL, CC, HH, bla);

    // ---- fused G5 + softmax -> attn fp16 ----
    mma_g5sm<<<MROWS / 128, 256, G5SMEM>>>();

    // ---- G7 + fusion_partial ----
    mma_gemm_fuse<<<dim3(CC / 128, MROWS / 128), 256, F7SMEM>>>();

    // ---- fusion + final projection ----
    fusion_reduce<<<BB, 512>>>();
    final_gemm<<<dim3(BB, HH / 256), 256>>>(Wp, out);
}

// round 17
// speedup vs baseline: 1.0949x; 1.0949x over previous
#include <cuda_runtime.h>
#include <cuda_fp16.h>
#include <cstdint>
#include <cstddef>

// Problem dims (fixed)
#define BB 16
#define SS 2048
#define LL 256
#define HH 768
#define CC 512
#define MROWS (BB*SS)   // 32768

// ---------------- one static scratch pool, byte-addressed -------------------
constexpr size_t SZ_IT     = (size_t)MROWS * CC * 2;
constexpr size_t SZ_LOGITS = (size_t)MROWS * LL * 4;
constexpr size_t SZ_FP     = (size_t)256 * CC * 4;
constexpr size_t SZ_FU     = (size_t)BB * CC * 4;
constexpr size_t SZ_X2     = (size_t)MROWS * HH * 2;
constexpr size_t SZ_LAB2   = (size_t)LL * HH * 2;
constexpr size_t SZ_WT2    = (size_t)CC * HH * 2;
constexpr size_t SZ_IA2    = (size_t)MROWS * CC * 2;
constexpr size_t SZ_ATT2   = (size_t)MROWS * LL * 2;
constexpr size_t SZ_LC2    = (size_t)LL * CC * 2;

constexpr size_t OFF_IT     = 0;
constexpr size_t OFF_LOGITS = OFF_IT + SZ_IT;
constexpr size_t OFF_FP     = OFF_LOGITS + SZ_LOGITS;
constexpr size_t OFF_FU     = OFF_FP + SZ_FP;
constexpr size_t OFF_XH     = OFF_FU + SZ_FU;           // x fp16
constexpr size_t OFF_LABH   = OFF_XH + SZ_X2;           // lab fp16
constexpr size_t OFF_WIH    = OFF_LABH + SZ_LAB2;       // Wi fp16
constexpr size_t OFF_WLH    = OFF_WIH + SZ_WT2;         // Wl fp16
constexpr size_t OFF_WIAH   = OFF_WLH + SZ_WT2;         // Wia fp16
constexpr size_t OFF_WLAH   = OFF_WIAH + SZ_WT2;        // Wla fp16
constexpr size_t OFF_IAH    = OFF_WLAH + SZ_WT2;        // ia fp16
constexpr size_t OFF_ATTH   = OFF_IAH + SZ_IA2;         // attn fp16
constexpr size_t OFF_LTH    = OFF_ATTH + SZ_ATT2;       // ltT fp16 [512,256]
constexpr size_t OFF_LAH    = OFF_LTH + SZ_LC2;         // la fp16 [256,512]
constexpr size_t POOL_BYTES = OFF_LAH + SZ_LC2;

__device__ __align__(16) unsigned char g_pool[POOL_BYTES];

// ---------------- helpers ---------------------------------------------------
__device__ __forceinline__ uint32_t smem_u32(const void* p) {
    uint32_t a;
    asm("{ .reg .u64 t; cvta.to.shared.u64 t, %1; cvt.u32.u64 %0, t; }" : "=r"(a) : "l"(p));
    return a;
}
__device__ __forceinline__ void cp16(uint32_t dst, const void* src) {
    asm volatile("cp.async.cg.shared.global [%0], [%1], 16;" :: "r"(dst), "l"(src) : "memory");
}
__device__ __forceinline__ void cp32(uint32_t dst, const void* src) {
    cp16(dst, src);
    cp16(dst + 16, (const char*)src + 16);
}
#define CP_COMMIT() asm volatile("cp.async.commit_group;" ::: "memory")
#define CP_WAIT0()  asm volatile("cp.async.wait_group 0;"  ::: "memory")

#define LDSM4(R0,R1,R2,R3,ADDR) \
    asm volatile("ldmatrix.sync.aligned.m8n8.x4.shared.b16 {%0,%1,%2,%3}, [%4];" \
                 : "=r"(R0),"=r"(R1),"=r"(R2),"=r"(R3) : "r"(ADDR))

#define MMA_F16F32(C,A,B0,B1) \
    asm volatile("mma.sync.aligned.m16n8k16.row.col.f32.f16.f16.f32 " \
                 "{%0,%1,%2,%3},{%4,%5,%6,%7},{%8,%9},{%0,%1,%2,%3};" \
                 : "+f"((C)[0]),"+f"((C)[1]),"+f"((C)[2]),"+f"((C)[3]) \
                 : "r"((A)[0]),"r"((A)[1]),"r"((A)[2]),"r"((A)[3]), \
                   "r"(B0),"r"(B1))

#define MMA_F16ACC(C0,C1,A,B0,B1) \
    asm volatile("mma.sync.aligned.m16n8k16.row.col.f16.f16.f16.f16 " \
                 "{%0,%1},{%2,%3,%4,%5},{%6,%7},{%0,%1};" \
                 : "+r"(C0),"+r"(C1) \
                 : "r"((A)[0]),"r"((A)[1]),"r"((A)[2]),"r"((A)[3]), \
                   "r"(B0),"r"(B1))

__device__ __forceinline__ float sigmoidf_(float v) {
    return 1.0f / (1.0f + __expf(-v));
}

// ---------------- input conversion: fp32 -> fp16 ------------------------------
__global__ __launch_bounds__(256)
void kconv_f16(const float4* __restrict__ src, size_t oH, int n4)
{
    int i = blockIdx.x * 256 + threadIdx.x;
    if (i >= n4) return;
    half2* h = (half2*)(g_pool + oH);
    float4 v = src[i];
    h[i * 2 + 0] = __floats2half2_rn(v.x, v.y);
    h[i * 2 + 1] = __floats2half2_rn(v.z, v.w);
}

// ---------------- shared tile geometry ---------------------------------------
#define SROW  80
#define TILEB (128 * SROW)  // 10240

enum { EPI_NONE = 0, EPI_SIGC = 1, EPI_SIGR = 3 };

// ---------------- generic fp16 1-product GEMM (f32 accum) --------------------
// C[M,N] = epi(A @ B^T); A [M,K] fp16, B [N,K] fp16.
// EPI_NONE -> fp32 out; EPI_SIGC/SIGR -> sigmoid(+bias) fp16 out.
#define FSTG (2 * TILEB)
#define FGSMEM (2 * FSTG)  // 40960

template<int EPI>
__global__ __launch_bounds__(256, 2)
void mma_f16(size_t oA, size_t oB, size_t oC,
             int N, int K, const float* __restrict__ bias)
{
    const __half* Ah = (const __half*)(g_pool + oA);
    const __half* Bh = (const __half*)(g_pool + oB);
    float* Cf  = (float*)(g_pool + oC);
    __half* Ch = (__half*)(g_pool + oC);

    extern __shared__ char smem[];
    const uint32_t sb = smem_u32(smem);
    const int tid  = threadIdx.x;
    const int lane = tid & 31;
    const int wid  = tid >> 5;
    const int wm   = wid & 3;
    const int wn   = wid >> 2;
    const int m0 = blockIdx.y * 128;
    const int n0 = blockIdx.x * 128;

    const int lr = tid >> 1;
    const int lh = tid & 1;
    const __half* gAh = Ah + (size_t)(m0 + lr) * K + lh * 16;
    const __half* gBh = Bh + (size_t)(n0 + lr) * K + lh * 16;
    const uint32_t sdst = (uint32_t)(lr * SROW + lh * 32);

    const int NCH = K / 32;
    float c[2][8][4] = {};

    {
        uint32_t d = sb + sdst;
        cp32(d,         gAh);
        cp32(d + TILEB, gBh);
        CP_COMMIT();
        CP_WAIT0();
        __syncthreads();
    }

    for (int ch = 0; ch < NCH; ch++) {
        if (ch + 1 < NCH) {
            const int k0 = (ch + 1) * 32;
            uint32_t d = sb + ((ch + 1) & 1) * FSTG + sdst;
            cp32(d,         gAh + k0);
            cp32(d + TILEB, gBh + k0);
            CP_COMMIT();
        }

        const uint32_t base = sb + (ch & 1) * FSTG;
        #pragma unroll
        for (int ks = 0; ks < 2; ks++) {
            uint32_t ah[2][4];
            #pragma unroll
            for (int mf = 0; mf < 2; mf++) {
                uint32_t addr = base
                    + (uint32_t)((wm * 32 + mf * 16 + (lane & 15)) * SROW)
                    + (uint32_t)(ks * 32 + (lane >> 4) * 16);
                LDSM4(ah[mf][0], ah[mf][1], ah[mf][2], ah[mf][3], addr);
            }
            const int g = lane >> 3;
            #pragma unroll
            for (int p = 0; p < 4; p++) {
                uint32_t addr = base + TILEB
                    + (uint32_t)((wn * 64 + p * 16 + ((g & 2) ? 8 : 0) + (lane & 7)) * SROW)
                    + (uint32_t)(ks * 32 + (g & 1) * 16);
                uint32_t h0, h1, h2, h3;
                LDSM4(h0, h1, h2, h3, addr);
                #pragma unroll
                for (int mf = 0; mf < 2; mf++) {
                    MMA_F16F32(c[mf][2*p],   ah[mf], h0, h1);
                    MMA_F16F32(c[mf][2*p+1], ah[mf], h2, h3);
                }
            }
        }
        if (ch + 1 < NCH) CP_WAIT0();
        __syncthreads();
    }

    const int quad = lane >> 2;
    const int tq   = lane & 3;
    #pragma unroll
    for (int mf = 0; mf < 2; mf++) {
        const int r0 = m0 + wm * 32 + mf * 16 + quad;
        const int r1 = r0 + 8;
        float rb0 = 0.f, rb1 = 0.f;
        if (EPI == EPI_SIGR) { rb0 = bias[r0]; rb1 = bias[r1]; }
        #pragma unroll
        for (int nf = 0; nf < 8; nf++) {
            const int col = n0 + wn * 64 + nf * 8 + tq * 2;
            float v0 = c[mf][nf][0], v1 = c[mf][nf][1];
            float v2 = c[mf][nf][2], v3 = c[mf][nf][3];
            if (EPI == EPI_SIGC) {
                float2 bb = *(const float2*)(bias + col);
                v0 = sigmoidf_(v0 + bb.x); v1 = sigmoidf_(v1 + bb.y);
                v2 = sigmoidf_(v2 + bb.x); v3 = sigmoidf_(v3 + bb.y);
            } else if (EPI == EPI_SIGR) {
                v0 = sigmoidf_(v0 + rb0); v1 = sigmoidf_(v1 + rb0);
                v2 = sigmoidf_(v2 + rb1); v3 = sigmoidf_(v3 + rb1);
            }
            if (EPI == EPI_NONE) {
                *(float2*)(Cf + (size_t)r0 * N + col) = make_float2(v0, v1);
                *(float2*)(Cf + (size_t)r1 * N + col) = make_float2(v2, v3);
            } else {
                *(half2*)(Ch + (size_t)r0 * N + col) = __floats2half2_rn(v0, v1);
                *(half2*)(Ch + (size_t)r1 * N + col) = __floats2half2_rn(v2, v3);
            }
        }
    }
}

// ---------------- dual GEMM: 256 thr, occ 2; both outputs per warp -----------
#define DSTAGEB (3 * TILEB)       // 30720
#define DGSMEM  (2 * DSTAGEB)     // 61440

__global__ __launch_bounds__(256, 2)
void mma_gemm_dual2(const float* __restrict__ bias_i,
                    const float* __restrict__ bias_ia,
                    const float* __restrict__ ctx)
{
    extern __shared__ char smem[];
    const uint32_t sb = smem_u32(smem);
    const int tid  = threadIdx.x;
    const int lane = tid & 31;
    const int wid  = tid >> 5;
    const int wm   = wid & 3;
    const int wn   = wid >> 2;
    const int m0 = blockIdx.y * 128;
    const int n0 = blockIdx.x * 128;
    const int K = HH;

    const __half* srcp[6];
    uint32_t dstp[6];
    {
        const __half* baseA  = (const __half*)(g_pool + OFF_XH);
        const __half* baseB0 = (const __half*)(g_pool + OFF_WIH);
        const __half* baseB1 = (const __half*)(g_pool + OFF_WIAH);
        #pragma unroll
        for (int t = 0; t < 6; t++) {
            int c2 = tid + t * 256;
            int tile = c2 >> 9;
            int pos  = c2 & 511;
            int row  = pos >> 2;
            int q    = pos & 3;
            const __half* bp;
            int rbase;
            switch (tile) {
                case 0: bp = baseA;  rbase = m0; break;
                case 1: bp = baseB0; rbase = n0; break;
                default: bp = baseB1; rbase = n0; break;
            }
            srcp[t] = bp + (size_t)(rbase + row) * K + q * 8;
            dstp[t] = (uint32_t)(tile * TILEB + row * SROW + q * 16);
        }
    }

    const int NCH = K / 32;
    uint32_t cit[2][8][2] = {};
    uint32_t cia[2][8][2] = {};

    {
        #pragma unroll
        for (int t = 0; t < 6; t++)
            cp16(sb + dstp[t], srcp[t]);
        CP_COMMIT();
        CP_WAIT0();
        __syncthreads();
    }

    for (int ch = 0; ch < NCH; ch++) {
        if (ch + 1 < NCH) {
            const int k0 = (ch + 1) * 32;
            const uint32_t stg = sb + ((ch + 1) & 1) * DSTAGEB;
            #pragma unroll
            for (int t = 0; t < 6; t++)
                cp16(stg + dstp[t], srcp[t] + k0);
            CP_COMMIT();
        }

        const uint32_t base = sb + (ch & 1) * DSTAGEB;
        #pragma unroll
        for (int ks = 0; ks < 2; ks++) {
            uint32_t ah[2][4];
            #pragma unroll
            for (int mf = 0; mf < 2; mf++) {
                uint32_t addr = base
                    + (uint32_t)((wm * 32 + mf * 16 + (lane & 15)) * SROW)
                    + (uint32_t)(ks * 32 + (lane >> 4) * 16);
                LDSM4(ah[mf][0], ah[mf][1], ah[mf][2], ah[mf][3], addr);
            }
            const int g = lane >> 3;
            #pragma unroll
            for (int p = 0; p < 4; p++) {
                uint32_t addr = base + TILEB
                    + (uint32_t)((wn * 64 + p * 16 + ((g & 2) ? 8 : 0) + (lane & 7)) * SROW)
                    + (uint32_t)(ks * 32 + (g & 1) * 16);
                uint32_t h0, h1, h2, h3;
                LDSM4(h0, h1, h2, h3, addr);
                #pragma unroll
                for (int mf = 0; mf < 2; mf++) {
                    MMA_F16ACC(cit[mf][2*p][0],   cit[mf][2*p][1],   ah[mf], h0, h1);
                    MMA_F16ACC(cit[mf][2*p+1][0], cit[mf][2*p+1][1], ah[mf], h2, h3);
                }
                LDSM4(h0, h1, h2, h3, addr + TILEB);
                #pragma unroll
                for (int mf = 0; mf < 2; mf++) {
                    MMA_F16ACC(cia[mf][2*p][0],   cia[mf][2*p][1],   ah[mf], h0, h1);
                    MMA_F16ACC(cia[mf][2*p+1][0], cia[mf][2*p+1][1], ah[mf], h2, h3);
                }
            }
        }
        if (ch + 1 < NCH) CP_WAIT0();
        __syncthreads();
    }

    const int quad = lane >> 2;
    const int tq   = lane & 3;
    __half* Cit = (__half*)(g_pool + OFF_IT);
    __half* Cia = (__half*)(g_pool + OFF_IAH);
    #pragma unroll
    for (int mf = 0; mf < 2; mf++) {
        const int r0 = m0 + wm * 32 + mf * 16 + quad;
        const int r1 = r0 + 8;
        #pragma unroll
        for (int nf = 0; nf < 8; nf++) {
            const int col = n0 + wn * 64 + nf * 8 + tq * 2;
            float2 bbi = *(const float2*)(bias_i + col);
            float2 bba = *(const float2*)(bias_ia + col);
            float2 ss  = *(const float2*)(ctx + col);
            float2 a01 = __half22float2(*(half2*)&cit[mf][nf][0]);
            float2 a23 = __half22float2(*(half2*)&cit[mf][nf][1]);
            *(half2*)(Cit + (size_t)r0 * CC + col) =
                __floats2half2_rn(sigmoidf_(a01.x + bbi.x), sigmoidf_(a01.y + bbi.y));
            *(half2*)(Cit + (size_t)r1 * CC + col) =
                __floats2half2_rn(sigmoidf_(a23.x + bbi.x), sigmoidf_(a23.y + bbi.y));
            a01 = __half22float2(*(half2*)&cia[mf][nf][0]);
            a23 = __half22float2(*(half2*)&cia[mf][nf][1]);
            *(half2*)(Cia + (size_t)r0 * CC + col) =
                __floats2half2_rn(sigmoidf_(a01.x + bba.x) * ss.x,
                                  sigmoidf_(a01.y + bba.y) * ss.y);
            *(half2*)(Cia + (size_t)r1 * CC + col) =
                __floats2half2_rn(sigmoidf_(a23.x + bba.x) * ss.x,
                                  sigmoidf_(a23.y + bba.y) * ss.y);
        }
    }
}

// ---------------- G7 + fusion (fp16 in, fp16 accum) --------------------------
#define F7SMEM (2 * FSTG + 4 * 128 * 4)  // 43008

__global__ __launch_bounds__(256, 2)
void mma_gemm_fuse()
{
    const __half* Ah = (const __half*)(g_pool + OFF_ATTH);
    const __half* Bh = (const __half*)(g_pool + OFF_LTH);
    const __half* itp = (const __half*)(g_pool + OFF_IT);
    float* fpart = (float*)(g_pool + OFF_FP);

    extern __shared__ char smem[];
    const uint32_t sb = smem_u32(smem);
    float* facc = (float*)(smem + 2 * FSTG);
    const int tid  = threadIdx.x;
    const int lane = tid & 31;
    const int wid  = tid >> 5;
    const int wm   = wid & 3;
    const int wn   = wid >> 2;
    const int m0 = blockIdx.y * 128;
    const int n0 = blockIdx.x * 128;
    const int K = LL;

    const int lr = tid >> 1;
    const int lh = tid & 1;
    const __half* gAh = Ah + (size_t)(m0 + lr) * K + lh * 16;
    const __half* gBh = Bh + (size_t)(n0 + lr) * K + lh * 16;
    const uint32_t sdst = (uint32_t)(lr * SROW + lh * 32);

    const int NCH = K / 32;
    uint32_t c[2][8][2] = {};

    {
        uint32_t d = sb + sdst;
        cp32(d,         gAh);
        cp32(d + TILEB, gBh);
        CP_COMMIT();
        CP_WAIT0();
        __syncthreads();
    }

    for (int ch = 0; ch < NCH; ch++) {
        if (ch + 1 < NCH) {
            const int k0 = (ch + 1) * 32;
            uint32_t d = sb + ((ch + 1) & 1) * FSTG + sdst;
            cp32(d,         gAh + k0);
            cp32(d + TILEB, gBh + k0);
            CP_COMMIT();
        }

        const uint32_t base = sb + (ch & 1) * FSTG;
        #pragma unroll
        for (int ks = 0; ks < 2; ks++) {
            uint32_t ah[2][4];
            #pragma unroll
            for (int mf = 0; mf < 2; mf++) {
                uint32_t addr = base
                    + (uint32_t)((wm * 32 + mf * 16 + (lane & 15)) * SROW)
                    + (uint32_t)(ks * 32 + (lane >> 4) * 16);
                LDSM4(ah[mf][0], ah[mf][1], ah[mf][2], ah[mf][3], addr);
            }
            const int g = lane >> 3;
            #pragma unroll
            for (int p = 0; p < 4; p++) {
                uint32_t addr = base + TILEB
                    + (uint32_t)((wn * 64 + p * 16 + ((g & 2) ? 8 : 0) + (lane & 7)) * SROW)
                    + (uint32_t)(ks * 32 + (g & 1) * 16);
                uint32_t h0, h1, h2, h3;
                LDSM4(h0, h1, h2, h3, addr);
                #pragma unroll
                for (int mf = 0; mf < 2; mf++) {
                    MMA_F16ACC(c[mf][2*p][0],   c[mf][2*p][1],   ah[mf], h0, h1);
                    MMA_F16ACC(c[mf][2*p+1][0], c[mf][2*p+1][1], ah[mf], h2, h3);
                }
            }
        }
        if (ch + 1 < NCH) CP_WAIT0();
        __syncthreads();
    }

    const int quad = lane >> 2;
    const int tq   = lane & 3;
    float pc[16];
    #pragma unroll
    for (int i = 0; i < 16; i++) pc[i] = 0.0f;
    #pragma unroll
    for (int mf = 0; mf < 2; mf++) {
        const int r0g = m0 + wm * 32 + mf * 16 + quad;
        const int r1g = r0g + 8;
        #pragma unroll
        for (int nf = 0; nf < 8; nf++) {
            const int colg = n0 + wn * 64 + nf * 8 + tq * 2;
            float2 w01 = __half22float2(*(half2*)&c[mf][nf][0]);
            float2 w23 = __half22float2(*(half2*)&c[mf][nf][1]);
            float2 i0 = __half22float2(*(const half2*)(itp + (size_t)r0g * CC + colg));
            float2 i1 = __half22float2(*(const half2*)(itp + (size_t)r1g * CC + colg));
            pc[2*nf]   += w01.x * i0.x + w23.x * i1.x;
            pc[2*nf+1] += w01.y * i0.y + w23.y * i1.y;
        }
    }
    #pragma unroll
    for (int off = 4; off <= 16; off <<= 1)
        #pragma unroll
        for (int i = 0; i < 16; i++)
            pc[i] += __shfl_xor_sync(0xffffffff, pc[i], off);
    if (quad == 0) {
        #pragma unroll
        for (int nf = 0; nf < 8; nf++) {
            const int col = wn * 64 + nf * 8 + tq * 2;
            facc[wm * 128 + col]     = pc[2*nf];
            facc[wm * 128 + col + 1] = pc[2*nf+1];
        }
    }
    __syncthreads();
    if (tid < 128) {
        float s = facc[tid] + facc[128 + tid] + facc[256 + tid] + facc[384 + tid];
        fpart[(size_t)blockIdx.y * CC + n0 + tid] = s;
    }
}

// ---------------- softmax over L=256; writes fp16 attn -----------------------
__global__ __launch_bounds__(256)
void softmax256()
{
    const float* logits = (const float*)(g_pool + OFF_LOGITS);
    __half* atth = (__half*)(g_pool + OFF_ATTH);

    const int row = blockIdx.x * 8 + threadIdx.y;
    const int lane = threadIdx.x;
    const float* r = logits + (size_t)row * LL;

    float v[8];
    float mx = -1e30f;
    #pragma unroll
    for (int j = 0; j < 8; j++) {
        v[j] = r[lane + 32 * j];
        mx = fmaxf(mx, v[j]);
    }
    #pragma unroll
    for (int s = 16; s > 0; s >>= 1)
        mx = fmaxf(mx, __shfl_xor_sync(0xffffffff, mx, s));

    float sum = 0.0f;
    #pragma unroll
    for (int j = 0; j < 8; j++) {
        v[j] = __expf(v[j] - mx);
        sum += v[j];
    }
    #pragma unroll
    for (int s = 16; s > 0; s >>= 1)
        sum += __shfl_xor_sync(0xffffffff, sum, s);

    const float inv = 1.0f / sum;
    const size_t ro = (size_t)row * LL;
    #pragma unroll
    for (int j = 0; j < 8; j++)
        atth[ro + lane + 32 * j] = __float2half(v[j] * inv);
}

// ---------------- fusion reduce ----------------------------------------------
__global__ __launch_bounds__(512)
void fusion_reduce()
{
    const float* fp = (const float*)(g_pool + OFF_FP);
    float* fu = (float*)(g_pool + OFF_FU);
    const int b = blockIdx.x, cidx = threadIdx.x;
    float acc = 0.0f;
    #pragma unroll
    for (int k = 0; k < 16; k++)
        acc += fp[((size_t)b * 16 + k) * CC + cidx];
    fu[(size_t)b * CC + cidx] = acc;
}

// ---------------- final: out[b,h] = sum_c fusion[b,c] * Wp[h,c] -------------
__global__ __launch_bounds__(256)
void final_gemm(const float* __restrict__ Wp, float* __restrict__ out)
{
    __shared__ float fs[CC];
    const float* fu = (const float*)(g_pool + OFF_FU);
    const int b = blockIdx.x;
    const int h = blockIdx.y * 256 + threadIdx.x;

    for (int i = threadIdx.x; i < CC; i += 256)
        fs[i] = fu[(size_t)b * CC + i];
    __syncthreads();

    float acc = 0.0f;
    const float4* wp4 = (const float4*)(Wp + (size_t)h * CC);
    const float4* fs4 = (const float4*)fs;
    #pragma unroll 4
    for (int c4 = 0; c4 < CC / 4; c4++) {
        float4 w = wp4[c4], f = fs4[c4];
        acc += w.x * f.x + w.y * f.y + w.z * f.z + w.w * f.w;
    }
    out[(size_t)b * HH + h] = acc;
}

// ---------------- launch ----------------------------------------------------
extern "C" void kernel_launch(void* const* d_in, const int* in_sizes, int n_in,
                              void* d_out, int out_size)
{
    const float* x   = (const float*)d_in[0];
    const float* lab = (const float*)d_in[1];
    const float* Wi  = (const float*)d_in[2];
    const float* bi  = (const float*)d_in[3];
    const float* Wl  = (const float*)d_in[4];
    const float* bl  = (const float*)d_in[5];
    const float* Wia = (const float*)d_in[6];
    const float* bia = (const float*)d_in[7];
    const float* Wla = (const float*)d_in[8];
    const float* bla = (const float*)d_in[9];
    const float* ctx = (const float*)d_in[10];
    const float* Wp  = (const float*)d_in[11];
    float* out = (float*)d_out;

    cudaFuncSetAttribute(mma_f16<EPI_SIGR>, cudaFuncAttributeMaxDynamicSharedMemorySize, FGSMEM);
    cudaFuncSetAttribute(mma_f16<EPI_SIGC>, cudaFuncAttributeMaxDynamicSharedMemorySize, FGSMEM);
    cudaFuncSetAttribute(mma_f16<EPI_NONE>, cudaFuncAttributeMaxDynamicSharedMemorySize, FGSMEM);
    cudaFuncSetAttribute(mma_gemm_dual2,    cudaFuncAttributeMaxDynamicSharedMemorySize, DGSMEM);
    cudaFuncSetAttribute(mma_gemm_fuse,     cudaFuncAttributeMaxDynamicSharedMemorySize, F7SMEM);

    // ---- input conversions (all fp16) ----
    kconv_f16<<<(MROWS * HH / 4 + 255) / 256, 256>>>((const float4*)x,   OFF_XH,   MROWS * HH / 4);
    kconv_f16<<<(CC * HH / 4 + 255) / 256, 256>>>((const float4*)Wi,  OFF_WIH,  CC * HH / 4);
    kconv_f16<<<(CC * HH / 4 + 255) / 256, 256>>>((const float4*)Wia, OFF_WIAH, CC * HH / 4);
    kconv_f16<<<(LL * HH / 4 + 255) / 256, 256>>>((const float4*)lab, OFF_LABH, LL * HH / 4);
    kconv_f16<<<(CC * HH / 4 + 255) / 256, 256>>>((const float4*)Wl,  OFF_WLH,  CC * HH / 4);
    kconv_f16<<<(CC * HH / 4 + 255) / 256, 256>>>((const float4*)Wla, OFF_WLAH, CC * HH / 4);

    // ---- fused G3+G4: it, ia' (fp16, occ-2 dual) ----
    mma_gemm_dual2<<<dim3(CC / 128, MROWS / 128), 256, DGSMEM>>>(bi, bia, ctx);

    // ---- G1: ltT[c,l] = sigmoid(Wl @ lab^T + bl[row])  [512,256], K=768 ----
    mma_f16<EPI_SIGR><<<dim3(LL / 128, CC / 128), 256, FGSMEM>>>(
        OFF_WLH, OFF_LABH, OFF_LTH, LL, HH, bl);

    // ---- G2: la[l,c] = sigmoid(lab @ Wla^T + bla[col]) [256,512], K=768 ----
    mma_f16<EPI_SIGC><<<dim3(CC / 128, LL / 128), 256, FGSMEM>>>(
        OFF_LABH, OFF_WLAH, OFF_LAH, CC, HH, bla);

    // ---- G5: logits = ia' @ la^T (fp16 in, fp32 accum/out) ----
    mma_f16<EPI_NONE><<<dim3(LL / 128, MROWS / 128), 256, FGSMEM>>>(
        OFF_IAH, OFF_LAH, OFF_LOGITS, LL, CC, nullptr);

    // ---- softmax -> attn fp16 ----
    softmax256<<<MROWS / 8, dim3(32, 8)>>>();

    // ---- G7 + fusion_partial ----
    mma_gemm_fuse<<<dim3(CC / 128, MROWS / 128), 256, F7SMEM>>>();

    // ---- fusion + final projection ----
    fusion_reduce<<<BB, 512>>>();
    final_gemm<<<dim3(BB, HH / 256), 256>>>(Wp, out);
}